// round 17
// baseline (speedup 1.0000x reference)
#include <cuda_runtime.h>

#define NQ 25
#define KVD 9
#define ROW 225
#define WPB 8              // warps per block
#define SPW 3              // samples per warp
#define SPB (WPB*SPW)      // 24 samples per block
#define THREADS (WPB*32)   // 256
#define RSTRIDE 18         // u64 per merged K|V|Q row (144B; 16 mod 128 -> 8 bank offsets)

typedef unsigned long long u64;

__device__ __forceinline__ u64 pk(float lo, float hi) {
    u64 r; asm("mov.b64 %0,{%1,%2};" : "=l"(r) : "f"(lo), "f"(hi)); return r;
}
__device__ __forceinline__ void unpk(u64 v, float& lo, float& hi) {
    asm("mov.b64 {%0,%1},%2;" : "=f"(lo), "=f"(hi) : "l"(v));
}
__device__ __forceinline__ u64 fma2(u64 a, u64 b, u64 c) {
    u64 d; asm("fma.rn.f32x2 %0,%1,%2,%3;" : "=l"(d) : "l"(a), "l"(b), "l"(c)); return d;
}
__device__ __forceinline__ u64 mul2(u64 a, u64 b) {
    u64 d; asm("mul.rn.f32x2 %0,%1,%2;" : "=l"(d) : "l"(a), "l"(b)); return d;
}
__device__ __forceinline__ u64 add2(u64 a, u64 b) {
    u64 d; asm("add.rn.f32x2 %0,%1,%2;" : "=l"(d) : "l"(a), "l"(b)); return d;
}

// Dynamic smem layout (u64 units):
#define OFF_W   0
#define OFF_B   648
#define OFF_G   720
#define OFF_BT  726
#define OFF_M   732
#define OFF_KV  748
#define OFF_X   (OFF_KV + WPB*SPW*NQ*RSTRIDE)
#define DYN_U64 (OFF_X + (WPB*SPW*ROW + 1)/2)
#define DYN_BYTES (DYN_U64*8)

// Merged row layout (u64 idx):
//  [0..3]=k pairs  [4]=(k8, mask*-1e9)
//  [5]=(v0,v1) [6..8]=v pairs
//  [10..13]=q pairs [14]=(q8, 1)  [15..17]=pad

__global__ __launch_bounds__(THREADS, 2)
void attn_fused_kernel(
    const float* __restrict__ x,     const float* __restrict__ mask,
    const float* __restrict__ Wq,    const float* __restrict__ bq,
    const float* __restrict__ Wk,    const float* __restrict__ bk,
    const float* __restrict__ Wv,    const float* __restrict__ bv,
    const float* __restrict__ gamma, const float* __restrict__ beta,
    float* __restrict__ out, int B)
{
    extern __shared__ __align__(16) u64 dyn[];
    u64* sW  = dyn + OFF_W;     // [pr][g][d][6]
    u64* sB  = dyn + OFF_B;     // [pr][g][6]
    u64* sG  = dyn + OFF_G;
    u64* sBt = dyn + OFF_BT;
    float* sMask = (float*)(dyn + OFF_M);

    const int tid  = threadIdx.x;
    const int warp = tid >> 5;
    const int lane = tid & 31;

    u64* sKV = dyn + OFF_KV + warp * (SPW * NQ * RSTRIDE);
    float* sX = (float*)(dyn + OFF_X) + warp * (SPW * ROW);

    // ---- repack constants (Wq,bq pre-scaled 1/3; q aug = 1, k aug = mask*-1e9) ----
    for (int i = tid; i < 540; i += THREADS) {
        const int p  = i % 5;
        const int d  = (i / 5) % KVD;
        const int g  = (i / 45) % 4;
        const int pr = i / 180;
        const float* W = (pr == 0) ? Wq : (pr == 1) ? Wk : Wv;
        const float sc = (pr == 0) ? (1.0f / 3.0f) : 1.0f;
        const int e = 2 * p;
        const float lo = W[g * 81 + e * KVD + d] * sc;
        const float hi = (e + 1 < KVD) ? W[g * 81 + (e + 1) * KVD + d] * sc : 0.f;
        sW[((pr * 4 + g) * KVD + d) * 6 + p] = pk(lo, hi);
    }
    for (int i = tid; i < 60; i += THREADS) {
        const int p  = i % 5;
        const int g  = (i / 5) % 4;
        const int pr = i / 20;
        const float* Bb = (pr == 0) ? bq : (pr == 1) ? bk : bv;
        const float sc = (pr == 0) ? (1.0f / 3.0f) : 1.0f;
        const int e = 2 * p;
        const float lo = Bb[g * KVD + e] * sc;
        float hi;
        if (e + 1 < KVD) hi = Bb[g * KVD + e + 1] * sc;
        else             hi = (pr == 0) ? 1.0f : 0.0f;
        sB[(pr * 4 + g) * 6 + p] = pk(lo, hi);
    }
    if (tid < 5) {
        const int e = 2 * tid;
        sG[tid]  = pk(gamma[e], (e + 1 < KVD) ? gamma[e + 1] : 0.f);
        sBt[tid] = pk(beta[e],  (e + 1 < KVD) ? beta[e + 1]  : 0.f);
    }
    if (tid < NQ) sMask[tid] = mask[tid] * -1e9f;
    __syncthreads();

    const long s0 = (long)blockIdx.x * SPB + warp * SPW;
    long nrem = (long)B - s0;
    const int cnt = (nrem <= 0) ? 0 : (nrem >= SPW ? SPW : (int)nrem);

    // ---- coalesced input staging ----
    {
        const float* xrow = x + s0 * ROW;
        const int total = cnt * ROW;
        for (int i = lane; i < total; i += 32) sX[i] = xrow[i];
    }
    __syncwarp();

    // ---- phase 1: lane = item; per-sample passes (reg lean) ----
    if (lane < NQ) {
        const int g = (lane < 3) ? 0 : (lane < 13) ? 1 : (lane < 23) ? 2 : 3;
        const float mterm = sMask[lane];
        const u64* wQ = sW + ((0 * 4 + g) * KVD) * 6;
        const u64* wK = sW + ((1 * 4 + g) * KVD) * 6;
        const u64* wV = sW + ((2 * 4 + g) * KVD) * 6;
        const u64* bQ = sB + (0 * 4 + g) * 6;
        const u64* bK = sB + (1 * 4 + g) * 6;
        const u64* bV = sB + (2 * 4 + g) * 6;

        #pragma unroll
        for (int s = 0; s < SPW; s++) {
            float xv[KVD];
            #pragma unroll
            for (int d = 0; d < KVD; d++) xv[d] = sX[s * ROW + lane * KVD + d];

            u64 aQ[5], aK[5], aV[5];
            #pragma unroll
            for (int p = 0; p < 5; p++) { aQ[p] = bQ[p]; aK[p] = bK[p]; aV[p] = bV[p]; }

            #pragma unroll
            for (int d = 0; d < KVD; d++) {
                const u64 xd = pk(xv[d], xv[d]);
                {
                    const u64* w = wQ + d * 6;
                    const ulonglong2 w01 = *(const ulonglong2*)w;
                    const ulonglong2 w23 = *(const ulonglong2*)(w + 2);
                    aQ[0]=fma2(xd,w01.x,aQ[0]); aQ[1]=fma2(xd,w01.y,aQ[1]);
                    aQ[2]=fma2(xd,w23.x,aQ[2]); aQ[3]=fma2(xd,w23.y,aQ[3]);
                    aQ[4]=fma2(xd,w[4], aQ[4]);
                }
                {
                    const u64* w = wK + d * 6;
                    const ulonglong2 w01 = *(const ulonglong2*)w;
                    const ulonglong2 w23 = *(const ulonglong2*)(w + 2);
                    aK[0]=fma2(xd,w01.x,aK[0]); aK[1]=fma2(xd,w01.y,aK[1]);
                    aK[2]=fma2(xd,w23.x,aK[2]); aK[3]=fma2(xd,w23.y,aK[3]);
                    aK[4]=fma2(xd,w[4], aK[4]);
                }
                {
                    const u64* w = wV + d * 6;
                    const ulonglong2 w01 = *(const ulonglong2*)w;
                    const ulonglong2 w23 = *(const ulonglong2*)(w + 2);
                    aV[0]=fma2(xd,w01.x,aV[0]); aV[1]=fma2(xd,w01.y,aV[1]);
                    aV[2]=fma2(xd,w23.x,aV[2]); aV[3]=fma2(xd,w23.y,aV[3]);
                    aV[4]=fma2(xd,w[4], aV[4]);
                }
            }

            u64* r = sKV + (s * NQ + lane) * RSTRIDE;
            float lo, hi; unpk(aK[4], lo, hi);
            *(ulonglong2*)(r + 0) = make_ulonglong2(aK[0], aK[1]);
            *(ulonglong2*)(r + 2) = make_ulonglong2(aK[2], aK[3]);
            r[4] = pk(lo, mterm);
            r[5] = aV[0];
            *(ulonglong2*)(r + 6) = make_ulonglong2(aV[1], aV[2]);
            *(ulonglong2*)(r + 8) = make_ulonglong2(aV[3], aV[4]);
            *(ulonglong2*)(r + 10) = make_ulonglong2(aQ[0], aQ[1]);
            *(ulonglong2*)(r + 12) = make_ulonglong2(aQ[2], aQ[3]);
            r[14] = aQ[4];
        }
    }
    __syncwarp();

    // ---- phase 2: 27 lanes = 3 samples x 9 lanes; 3 q-rows per lane ----
    if (lane < 27) {
        const int sel = lane / 9;
        const int idx = lane % 9;
        const int base_row = 3 * idx;        // rows base..base+2, clamp at 24

        const u64* sbase = sKV + sel * (NQ * RSTRIDE);

        u64 q[3][5];
        #pragma unroll
        for (int s = 0; s < 3; s++) {
            const int row = (base_row + s < NQ) ? base_row + s : NQ - 1;
            const u64* r = sbase + row * RSTRIDE;
            const ulonglong2 q01 = *(const ulonglong2*)(r + 10);
            const ulonglong2 q23 = *(const ulonglong2*)(r + 12);
            q[s][0] = q01.x; q[s][1] = q01.y;
            q[s][2] = q23.x; q[s][3] = q23.y;
            q[s][4] = r[14];
        }

        u64 o[3][5];
        float sum[3] = {0.f, 0.f, 0.f};
        #pragma unroll
        for (int s = 0; s < 3; s++)
            #pragma unroll
            for (int p = 0; p < 5; p++) o[s][p] = 0;

        #pragma unroll
        for (int j = 0; j < NQ; j++) {
            const u64* r = sbase + j * RSTRIDE;
            const ulonglong2 L0 = *(const ulonglong2*)(r + 0);
            const ulonglong2 L1 = *(const ulonglong2*)(r + 2);
            const ulonglong2 L2 = *(const ulonglong2*)(r + 4);  // (k8,m)(v0v1)
            const ulonglong2 L3 = *(const ulonglong2*)(r + 6);
            const ulonglong2 L4 = *(const ulonglong2*)(r + 8);
            u64 ep[3];
            #pragma unroll
            for (int s = 0; s < 3; s++) {
                u64 acc = mul2(q[s][0], L0.x);
                acc = fma2(q[s][1], L0.y, acc);
                acc = fma2(q[s][2], L1.x, acc);
                acc = fma2(q[s][3], L1.y, acc);
                acc = fma2(q[s][4], L2.x, acc);
                float lo, hi; unpk(acc, lo, hi);
                const float e = __expf(lo + hi);
                sum[s] += e;
                ep[s] = pk(e, e);
            }
            #pragma unroll
            for (int s = 0; s < 3; s++) {
                o[s][0] = fma2(ep[s], L2.y, o[s][0]);
                o[s][1] = fma2(ep[s], L3.x, o[s][1]);
                o[s][2] = fma2(ep[s], L3.y, o[s][2]);
                o[s][3] = fma2(ep[s], L4.x, o[s][3]);
                o[s][4] = fma2(ep[s], L4.y, o[s][4]);
            }
        }

        // ---- epilogue per q-row (skip clamped duplicates) ----
        const u64 g01 = sG[0], g1p = sG[1], g2p = sG[2], g3p = sG[3];
        const u64 b01 = sBt[0], b1p = sBt[1], b2p = sBt[2], b3p = sBt[3];
        float g8, b8, zz;
        unpk(sG[4], g8, zz); unpk(sBt[4], b8, zz);
        #pragma unroll
        for (int s = 0; s < 3; s++) {
            if (s > 0 && base_row + s >= NQ) break;
            const int row = base_row + s;
            float* sxS = sX + sel * ROW;
            float xr[KVD];
            #pragma unroll
            for (int d = 0; d < KVD; d++) xr[d] = sxS[row * KVD + d];

            const float inv = 1.0f / sum[s];
            const u64 inv2 = pk(inv, inv);
            const u64 f0 = fma2(o[s][0], inv2, pk(xr[0], xr[1]));
            const u64 f1 = fma2(o[s][1], inv2, pk(xr[2], xr[3]));
            const u64 f2 = fma2(o[s][2], inv2, pk(xr[4], xr[5]));
            const u64 f3 = fma2(o[s][3], inv2, pk(xr[6], xr[7]));
            const u64 f4 = fma2(o[s][4], inv2, pk(xr[8], 0.f));

            float e0,e1,e2,e3,e4,e5,e6,e7,e8,ez;
            unpk(f0, e0, e1); unpk(f1, e2, e3);
            unpk(f2, e4, e5); unpk(f3, e6, e7);
            unpk(f4, e8, ez);
            const float mu = (e0+e1+e2+e3+e4+e5+e6+e7+e8) * (1.0f/9.0f);
            const u64 nmu2 = pk(-mu, -mu);
            const u64 t0 = add2(f0, nmu2);
            const u64 t1 = add2(f1, nmu2);
            const u64 t2 = add2(f2, nmu2);
            const u64 t3 = add2(f3, nmu2);
            const float t8 = e8 - mu;
            u64 vacc = mul2(t0, t0);
            vacc = fma2(t1, t1, vacc);
            vacc = fma2(t2, t2, vacc);
            vacc = fma2(t3, t3, vacc);
            float va0, va1; unpk(vacc, va0, va1);
            const float var = (va0 + va1 + t8 * t8) * (1.0f/9.0f);
            const float rinv = rsqrtf(var + 1e-5f);
            const u64 rinv2 = pk(rinv, rinv);

            const u64 r0p = fma2(mul2(t0, rinv2), g01, b01);
            const u64 r1p = fma2(mul2(t1, rinv2), g1p, b1p);
            const u64 r2p = fma2(mul2(t2, rinv2), g2p, b2p);
            const u64 r3p = fma2(mul2(t3, rinv2), g3p, b3p);
            const float r8v = t8 * rinv * g8 + b8;

            float w0,w1,w2,w3,w4,w5,w6,w7;
            unpk(r0p,w0,w1); unpk(r1p,w2,w3); unpk(r2p,w4,w5); unpk(r3p,w6,w7);
            float* so = sxS + row * KVD;
            so[0]=w0; so[1]=w1; so[2]=w2; so[3]=w3;
            so[4]=w4; so[5]=w5; so[6]=w6; so[7]=w7; so[8]=r8v;
        }
    }
    __syncwarp();

    // ---- coalesced output ----
    {
        float* orow = out + s0 * ROW;
        const int total = cnt * ROW;
        for (int i = lane; i < total; i += 32) orow[i] = sX[i];
    }
}

extern "C" void kernel_launch(void* const* d_in, const int* in_sizes, int n_in,
                              void* d_out, int out_size)
{
    const float* x     = (const float*)d_in[0];
    const float* mask  = (const float*)d_in[1];
    const float* Wq    = (const float*)d_in[2];
    const float* bq    = (const float*)d_in[3];
    const float* Wk    = (const float*)d_in[4];
    const float* bk    = (const float*)d_in[5];
    const float* Wv    = (const float*)d_in[6];
    const float* bv    = (const float*)d_in[7];
    const float* gamma = (const float*)d_in[8];
    const float* beta  = (const float*)d_in[9];
    float* out = (float*)d_out;

    (void)cudaFuncSetAttribute(attn_fused_kernel,
                               cudaFuncAttributeMaxDynamicSharedMemorySize, DYN_BYTES);

    const int B = in_sizes[0] / ROW;
    const int blocks = (B + SPB - 1) / SPB;
    attn_fused_kernel<<<blocks, THREADS, DYN_BYTES>>>(x, mask, Wq, bq, Wk, bk,
                                                      Wv, bv, gamma, beta, out, B);
}